// round 7
// baseline (speedup 1.0000x reference)
#include <cuda_runtime.h>
#include <math.h>

#define B  32
#define L  128
#define H  512
#define EN 256
#define ET 512
#define VN 300
#define VO 10053
#define EOFT 9999
#define G4 2048
#define KG 1536
#define LDZ 10080        // z row stride
#define LDZP 10656       // padded Wg^T columns = 148*72
#define JT 72            // j-columns per kS3 block
#define PADW 36

// ------------- static device scratch (no allocations) -------------
__device__ float g_wihP[(EN + ET) * G4];      // [k][u*4+g]
__device__ float g_whhP[H * G4];              // [k][u*4+g]
__device__ float g_biasP[G4];                 // permuted b_ih+b_hh
__device__ float g_wgT[(size_t)KG * LDZP];    // [k][j], j >= VO zeroed
__device__ float g_TN[VN * G4];               // embN @ w_ihN^T (permuted cols)
__device__ float g_GX[B * L * G4];            // hoisted input-side gates
__device__ float g_h[2][B * H];
__device__ float g_c[2][B * H];
__device__ float g_hs[B * L * H];
__device__ float g_z[B * LDZ];
__device__ float g_tl[B * L];

// ------------- prep: permute w_ih / w_hh / bias -------------
__global__ void kPrep(const float* __restrict__ w_ih, const float* __restrict__ w_hh,
                      const float* __restrict__ b_ih, const float* __restrict__ b_hh) {
    const int n1 = G4 * (EN + ET), n2 = G4 * H;
    for (int i = blockIdx.x * blockDim.x + threadIdx.x; i < n1 + n2 + G4;
         i += gridDim.x * blockDim.x) {
        if (i < n1) {
            int j = i / (EN + ET), k = i % (EN + ET);
            g_wihP[k * G4 + (j & 511) * 4 + (j >> 9)] = w_ih[i];
        } else if (i < n1 + n2) {
            int e = i - n1;
            int j = e / H, k = e % H;
            g_whhP[k * G4 + (j & 511) * 4 + (j >> 9)] = w_hh[e];
        } else {
            int j = i - n1 - n2;
            g_biasP[(j & 511) * 4 + (j >> 9)] = b_ih[j] + b_hh[j];
        }
    }
}

// ------------- prep: transpose Wg_w [VO][KG] -> g_wgT[k][LDZP] -------------
__global__ void kPrepWg(const float* __restrict__ Wg_w) {
    __shared__ float tile[32][33];
    int j0 = blockIdx.x * 32, k0 = blockIdx.y * 32;
    int tx = threadIdx.x, ty = threadIdx.y;  // 32 x 8
#pragma unroll
    for (int i = 0; i < 32; i += 8) {
        int j = j0 + ty + i, k = k0 + tx;
        tile[ty + i][tx] = (j < VO) ? Wg_w[(size_t)j * KG + k] : 0.f;
    }
    __syncthreads();
#pragma unroll
    for (int i = 0; i < 32; i += 8) {
        int k = k0 + ty + i, j = j0 + tx;
        g_wgT[(size_t)k * LDZP + j] = tile[tx][ty + i];
    }
}

// ------------- prep: TN[v][j'] = embN[v] . w_ihN[j'] -------------
__global__ void __launch_bounds__(256) kTN(const float* __restrict__ embN) {
    __shared__ float se[8][EN];
    int t = threadIdx.x;
    int j = blockIdx.x * 256 + t;
    int v0 = blockIdx.y * 8;
    for (int f = t; f < 8 * EN; f += 256) {
        int vv = f >> 8, k = f & 255;
        int v = v0 + vv;
        se[vv][k] = (v < VN) ? embN[v * EN + k] : 0.f;
    }
    __syncthreads();
    float acc[8];
#pragma unroll
    for (int i = 0; i < 8; i++) acc[i] = 0.f;
    for (int k = 0; k < EN; k++) {
        float w = g_wihP[k * G4 + j];
#pragma unroll
        for (int vv = 0; vv < 8; vv++) acc[vv] += se[vv][k] * w;
    }
#pragma unroll
    for (int vv = 0; vv < 8; vv++) {
        int v = v0 + vv;
        if (v < VN) g_TN[v * G4 + j] = acc[vv];
    }
}

// ------------- prep: GX[(it*B+b)][j'] = TN[n] + embT[t].w_ihT + bias ------
__global__ void __launch_bounds__(256) kGX(const float* __restrict__ embT,
                                           const int* __restrict__ nT,
                                           const int* __restrict__ tT) {
    __shared__ float sx[64][PADW];
    __shared__ int sti[32], sni[32];
    int t = threadIdx.x;
    int jj = t & 63, rg = t >> 6;
    int it = blockIdx.y;
    int j = blockIdx.x * 64 + jj;
    if (t < 32) {
        sti[t] = (it == 0) ? 0 : tT[t * L + it - 1];
        sni[t] = (it == 0) ? 0 : nT[t * L + it - 1];
    }
    __syncthreads();
    float bs = g_biasP[j];
    float acc[8];
#pragma unroll
    for (int i = 0; i < 8; i++) acc[i] = g_TN[sni[rg * 8 + i] * G4 + j] + bs;
    for (int kc = 0; kc < ET; kc += 64) {
        __syncthreads();
        for (int f = t; f < 512; f += 256) {
            int rr = f >> 4, ks = f & 15;
            const float4 v = *(const float4*)&embT[(size_t)sti[rr] * ET + kc + ks * 4];
            sx[ks * 4 + 0][rr] = v.x; sx[ks * 4 + 1][rr] = v.y;
            sx[ks * 4 + 2][rr] = v.z; sx[ks * 4 + 3][rr] = v.w;
        }
        __syncthreads();
#pragma unroll 8
        for (int kk = 0; kk < 64; kk++) {
            float w = g_wihP[(EN + kc + kk) * G4 + j];
            float4 xa = *(float4*)&sx[kk][rg * 8];
            float4 xb = *(float4*)&sx[kk][rg * 8 + 4];
            acc[0] += xa.x * w; acc[1] += xa.y * w;
            acc[2] += xa.z * w; acc[3] += xa.w * w;
            acc[4] += xb.x * w; acc[5] += xb.y * w;
            acc[6] += xb.z * w; acc[7] += xb.w * w;
        }
    }
#pragma unroll
    for (int i = 0; i < 8; i++)
        g_GX[(size_t)(it * B + rg * 8 + i) * G4 + j] = acc[i];
}

// ------------- init h0/c0 -------------
__global__ void kInit() {
    int i = blockIdx.x * blockDim.x + threadIdx.x;
    if (i < B * H) { g_h[0][i] = 0.f; g_c[0][i] = 0.f; }
}

// ------------- S1 body: recurrent gates + cell update (128 threads) -------
// Thread (jj = t&3, bb = t>>2) owns all 4 gates of (batch bb, unit u).
__device__ __forceinline__ void s1_body(int it, int ublk, int t) {
    int p = it & 1, cur = p ^ 1;
    __shared__ float sh[64][33];
    int jj = t & 3, bb = t >> 2;
    int u = ublk * 4 + jj;
    float4 acc = make_float4(0.f, 0.f, 0.f, 0.f);
    for (int kc = 0; kc < H; kc += 64) {
        __syncthreads();
        for (int f = t; f < 512; f += 128) {
            int rr = f >> 4, ks = f & 15;
            const float4 v = *(const float4*)&g_h[p][rr * H + kc + ks * 4];
            sh[ks * 4 + 0][rr] = v.x; sh[ks * 4 + 1][rr] = v.y;
            sh[ks * 4 + 2][rr] = v.z; sh[ks * 4 + 3][rr] = v.w;
        }
        __syncthreads();
#pragma unroll 8
        for (int kk = 0; kk < 64; kk++) {
            const float4 w = *(const float4*)&g_whhP[(kc + kk) * G4 + u * 4];
            float x = sh[kk][bb];
            acc.x += w.x * x; acc.y += w.y * x;
            acc.z += w.z * x; acc.w += w.w * x;
        }
    }
    const float4 gx = *(const float4*)&g_GX[(size_t)(it * B + bb) * G4 + u * 4];
    float ig = acc.x + gx.x, fg = acc.y + gx.y;
    float gg = acc.z + gx.z, og = acc.w + gx.w;
    float cp = g_c[p][bb * H + u];
    float si = 1.f / (1.f + expf(-ig));
    float sf = 1.f / (1.f + expf(-fg));
    float so = 1.f / (1.f + expf(-og));
    float cn = sf * cp + si * tanhf(gg);
    float hn = so * tanhf(cn);
    g_c[cur][bb * H + u] = cn;
    g_h[cur][bb * H + u] = hn;
    g_hs[(size_t)(bb * L + it) * H + u] = hn;
}

// ------------- S4 body: s_t, z reductions, tl + topi (128 threads) -------
__device__ __forceinline__ void s4_body(int it, int b, int t, const int* __restrict__ tT,
                                        const float* __restrict__ Ws_w,
                                        const float* __restrict__ Ws_b,
                                        float* __restrict__ out, int out_size) {
    int cur = (it & 1) ^ 1;
    __shared__ float rf[128];
    __shared__ int ri[128];
    __shared__ float sS, sMx, sSz;
    __shared__ int sMi;

    // s_t = sigmoid([h,c] . Ws_w + Ws_b)
    float sp = 0.f;
    for (int k = t; k < 2 * H; k += 128)
        sp += ((k < H) ? g_h[cur][b * H + k] : g_c[cur][b * H + k - H]) * Ws_w[k];
    rf[t] = sp; __syncthreads();
    for (int s = 64; s; s >>= 1) { if (t < s) rf[t] += rf[t + s]; __syncthreads(); }
    if (t == 0) sS = 1.f / (1.f + expf(-(rf[0] + Ws_b[0])));
    __syncthreads();

    const float* zr = &g_z[b * LDZ];
    // pass 1: sum, max, argmax
    float mx = -3.4e38f; int mi = 0; float sz = 0.f;
    for (int jx = t; jx < VO; jx += 128) {
        float v = zr[jx];
        sz += v;
        if (v > mx) { mx = v; mi = jx; }
    }
    rf[t] = sz; __syncthreads();
    for (int s = 64; s; s >>= 1) { if (t < s) rf[t] += rf[t + s]; __syncthreads(); }
    if (t == 0) sSz = rf[0];
    __syncthreads();
    rf[t] = mx; ri[t] = mi; __syncthreads();
    for (int s = 64; s; s >>= 1) {
        if (t < s) {
            float v2 = rf[t + s]; int i2 = ri[t + s];
            if (v2 > rf[t] || (v2 == rf[t] && i2 < ri[t])) { rf[t] = v2; ri[t] = i2; }
        }
        __syncthreads();
    }
    if (t == 0) { sMx = rf[0]; sMi = ri[0]; }
    __syncthreads();
    // pass 2: sum exp(z - max)
    float mxv = sMx;
    float se = 0.f;
    for (int jx = t; jx < VO; jx += 128) se += expf(zr[jx] - mxv);
    rf[t] = se; __syncthreads();
    for (int s = 64; s; s >>= 1) { if (t < s) rf[t] += rf[t + s]; __syncthreads(); }
    if (t == 0) {
        float lse = mxv + logf(rf[0]);
        float s = sS;
        int tc = tT[b * L + it];
        float tl;
        if (tc == EOFT) tl = 0.f;
        else {
            float out_tc  = s * (zr[tc]   - lse);
            float out_eof = s * (zr[EOFT] - lse);
            float Ssum    = s * (sSz - (float)VO * lse);
            const float smv = 0.1f / (float)(VO - 2);
            tl = 0.1f * logf(smv) + 0.9f * logf(0.9f)
               - smv * (Ssum - out_eof - out_tc) - 0.9f * out_tc;
        }
        g_tl[it * B + b] = tl;
        int oi = 1 + b * L + it;
        if (oi < out_size) out[oi] = (float)sMi;
    }
}

// ------------- fused per-step kernel: S1(it) || S4(it-1) -------------
__global__ void __launch_bounds__(128) kFuse(int it, const int* __restrict__ tT,
                                             const float* __restrict__ Ws_w,
                                             const float* __restrict__ Ws_b,
                                             float* __restrict__ out, int out_size) {
    if (blockIdx.x < 128) {
        s1_body(it, blockIdx.x, threadIdx.x);
    } else if (it > 0) {
        s4_body(it - 1, blockIdx.x - 128, threadIdx.x, tT, Ws_w, Ws_b, out, out_size);
    }
}

// ------------- standalone S4 for the last step -------------
__global__ void __launch_bounds__(128) kS4Last(int it, const int* __restrict__ tT,
                                               const float* __restrict__ Ws_w,
                                               const float* __restrict__ Ws_b,
                                               float* __restrict__ out, int out_size) {
    s4_body(it, blockIdx.x, threadIdx.x, tT, Ws_w, Ws_b, out, out_size);
}

// ------------- per-step S3: z = [h,c,h_parent] @ Wg^T + b -------------
// 148 blocks x 288 threads; thread tile = 4 j x 2 b; FMA-bound inner loop.
__global__ void __launch_bounds__(288) kS3(int it, const int* __restrict__ pT,
                                           const float* __restrict__ Wg_b) {
    int cur = (it & 1) ^ 1;
    __shared__ float sx[64][33];
    __shared__ int spar[32];
    int t = threadIdx.x;
    int jj = t % 18, bg = t / 18;          // jj: 18 j-quads, bg: 16 b-pairs
    int j = blockIdx.x * JT + jj * 4;
    if (t < 32) {
        int par = (it == 0) ? 0 : pT[t * L + it - 1];
        spar[t] = (it > 0 && par < it) ? par : -1;
    }
    float acc[8];
#pragma unroll
    for (int i = 0; i < 8; i++) acc[i] = 0.f;
    for (int kc = 0; kc < KG; kc += 64) {
        __syncthreads();
        for (int f = t; f < 512; f += 288) {
            int rr = f >> 4, ks = f & 15;
            int k = kc + ks * 4;
            float4 v;
            if (k < H) v = *(const float4*)&g_h[cur][rr * H + k];
            else if (k < 2 * H) v = *(const float4*)&g_c[cur][rr * H + k - H];
            else {
                int par = spar[rr];
                v = (par >= 0) ? *(const float4*)&g_hs[(size_t)(rr * L + par) * H + k - 2 * H]
                               : make_float4(0.f, 0.f, 0.f, 0.f);
            }
            sx[ks * 4 + 0][rr] = v.x; sx[ks * 4 + 1][rr] = v.y;
            sx[ks * 4 + 2][rr] = v.z; sx[ks * 4 + 3][rr] = v.w;
        }
        __syncthreads();
#pragma unroll 8
        for (int kk = 0; kk < 64; kk++) {
            const float4 w = *(const float4*)&g_wgT[(size_t)(kc + kk) * LDZP + j];
            float x0 = sx[kk][bg * 2 + 0];
            float x1 = sx[kk][bg * 2 + 1];
            acc[0] += w.x * x0; acc[1] += w.y * x0;
            acc[2] += w.z * x0; acc[3] += w.w * x0;
            acc[4] += w.x * x1; acc[5] += w.y * x1;
            acc[6] += w.z * x1; acc[7] += w.w * x1;
        }
    }
    int b0 = bg * 2, b1 = bg * 2 + 1;
#pragma unroll
    for (int i = 0; i < 4; i++) {
        int jc = j + i;
        if (jc < VO) {
            float bb = Wg_b[jc];
            g_z[b0 * LDZ + jc] = acc[i] + bb;
            g_z[b1 * LDZ + jc] = acc[4 + i] + bb;
        }
    }
}

// ------------- final: sum tl, zero any tail -------------
__global__ void kFinal(float* __restrict__ out, int out_size) {
    __shared__ float rf[256];
    int t = threadIdx.x;
    float s = 0.f;
    for (int i = t; i < B * L; i += 256) s += g_tl[i];
    rf[t] = s; __syncthreads();
    for (int k = 128; k; k >>= 1) { if (t < k) rf[t] += rf[t + k]; __syncthreads(); }
    if (t == 0 && out_size > 0) out[0] = rf[0];
    for (int i = 1 + B * L + t; i < out_size; i += 256) out[i] = 0.f;
}

extern "C" void kernel_launch(void* const* d_in, const int* in_sizes, int n_in,
                              void* d_out, int out_size) {
    const int*   nT   = (const int*)d_in[0];
    const int*   tT   = (const int*)d_in[1];
    const int*   pT   = (const int*)d_in[2];
    const float* embN = (const float*)d_in[3];
    const float* embT = (const float*)d_in[4];
    const float* w_ih = (const float*)d_in[5];
    const float* w_hh = (const float*)d_in[6];
    const float* b_ih = (const float*)d_in[7];
    const float* b_hh = (const float*)d_in[8];
    // d_in[9..12] (Wh_w, Wh_b, v_w, v_b) are dead code — attention branch never wins.
    const float* Wg_w = (const float*)d_in[13];
    const float* Wg_b = (const float*)d_in[14];
    const float* Ws_w = (const float*)d_in[15];
    const float* Ws_b = (const float*)d_in[16];
    float* out = (float*)d_out;

    kPrep<<<1024, 256>>>(w_ih, w_hh, b_ih, b_hh);
    kPrepWg<<<dim3(LDZP / 32, KG / 32), dim3(32, 8)>>>(Wg_w);
    kTN<<<dim3(G4 / 256, (VN + 7) / 8), 256>>>(embN);
    kGX<<<dim3(G4 / 64, L), 256>>>(embT, nT, tT);
    kInit<<<(B * H + 255) / 256, 256>>>();

    for (int it = 0; it < L; ++it) {
        kFuse<<<160, 128>>>(it, tT, Ws_w, Ws_b, out, out_size);
        kS3<<<148, 288>>>(it, pT, Wg_b);
    }
    kS4Last<<<B, 128>>>(127, tT, Ws_w, Ws_b, out, out_size);
    kFinal<<<1, 256>>>(out, out_size);
}

// round 11
// speedup vs baseline: 1.5861x; 1.5861x over previous
#include <cuda_runtime.h>
#include <math.h>

#define B  32
#define L  128
#define H  512
#define EN 256
#define ET 512
#define VN 300
#define VO 10053
#define EOFT 9999
#define G4 2048
#define KG 1536
#define LDZ 10080        // z row stride (multiple of 32)
#define LDZ2 10656       // padded Wg^T columns = 333*32
#define JB 333           // j-blocks of 32 cols
#define PADW 36          // smem row pad: 36 floats = 144B, 16B-aligned rows

// ------------- static device scratch (no allocations) -------------
__device__ float g_wihP[(EN + ET) * G4];      // [k][u*4+g]
__device__ float g_whhP[H * G4];              // [k][u*4+g]
__device__ float g_biasP[G4];                 // permuted b_ih+b_hh
__device__ float g_wgT[(size_t)KG * LDZ2];    // [k][j], j >= VO zeroed
__device__ float g_TN[VN * G4];               // embN @ w_ihN^T (permuted cols)
__device__ float g_GX[B * L * G4];            // hoisted input-side gates
__device__ float g_h[2][B * H];
__device__ float g_c[2][B * H];
__device__ float g_hs[B * L * H];
__device__ float g_z0[B * LDZ];               // K-split partial (k < 768), includes bias
__device__ float g_z1[B * LDZ];               // K-split partial (k >= 768)
__device__ float g_tl[B * L];

// ------------- prep: permute w_ih / w_hh / bias -------------
__global__ void kPrep(const float* __restrict__ w_ih, const float* __restrict__ w_hh,
                      const float* __restrict__ b_ih, const float* __restrict__ b_hh) {
    const int n1 = G4 * (EN + ET), n2 = G4 * H;
    for (int i = blockIdx.x * blockDim.x + threadIdx.x; i < n1 + n2 + G4;
         i += gridDim.x * blockDim.x) {
        if (i < n1) {
            int j = i / (EN + ET), k = i % (EN + ET);
            g_wihP[k * G4 + (j & 511) * 4 + (j >> 9)] = w_ih[i];
        } else if (i < n1 + n2) {
            int e = i - n1;
            int j = e / H, k = e % H;
            g_whhP[k * G4 + (j & 511) * 4 + (j >> 9)] = w_hh[e];
        } else {
            int j = i - n1 - n2;
            g_biasP[(j & 511) * 4 + (j >> 9)] = b_ih[j] + b_hh[j];
        }
    }
}

// ------------- prep: transpose Wg_w [VO][KG] -> g_wgT[k][LDZ2] -------------
__global__ void kPrepWg(const float* __restrict__ Wg_w) {
    __shared__ float tile[32][33];
    int j0 = blockIdx.x * 32, k0 = blockIdx.y * 32;
    int tx = threadIdx.x, ty = threadIdx.y;  // 32 x 8
#pragma unroll
    for (int i = 0; i < 32; i += 8) {
        int j = j0 + ty + i, k = k0 + tx;
        tile[ty + i][tx] = (j < VO) ? Wg_w[(size_t)j * KG + k] : 0.f;
    }
    __syncthreads();
#pragma unroll
    for (int i = 0; i < 32; i += 8) {
        int k = k0 + ty + i, j = j0 + tx;
        g_wgT[(size_t)k * LDZ2 + j] = tile[tx][ty + i];
    }
}

// ------------- prep: TN[v][j'] = embN[v] . w_ihN[j'] -------------
__global__ void __launch_bounds__(256) kTN(const float* __restrict__ embN) {
    __shared__ float se[8][EN];
    int t = threadIdx.x;
    int j = blockIdx.x * 256 + t;
    int v0 = blockIdx.y * 8;
    for (int f = t; f < 8 * EN; f += 256) {
        int vv = f >> 8, k = f & 255;
        int v = v0 + vv;
        se[vv][k] = (v < VN) ? embN[v * EN + k] : 0.f;
    }
    __syncthreads();
    float acc[8];
#pragma unroll
    for (int i = 0; i < 8; i++) acc[i] = 0.f;
    for (int k = 0; k < EN; k++) {
        float w = g_wihP[k * G4 + j];
#pragma unroll
        for (int vv = 0; vv < 8; vv++) acc[vv] += se[vv][k] * w;
    }
#pragma unroll
    for (int vv = 0; vv < 8; vv++) {
        int v = v0 + vv;
        if (v < VN) g_TN[v * G4 + j] = acc[vv];
    }
}

// ------------- prep: GX[(it*B+b)][j'] = TN[n] + embT[t].w_ihT + bias ------
__global__ void __launch_bounds__(256) kGX(const float* __restrict__ embT,
                                           const int* __restrict__ nT,
                                           const int* __restrict__ tT) {
    __shared__ float sx[64][PADW];
    __shared__ int sti[32], sni[32];
    int t = threadIdx.x;
    int jj = t & 63, rg = t >> 6;
    int it = blockIdx.y;
    int j = blockIdx.x * 64 + jj;
    if (t < 32) {
        sti[t] = (it == 0) ? 0 : tT[t * L + it - 1];
        sni[t] = (it == 0) ? 0 : nT[t * L + it - 1];
    }
    __syncthreads();
    float bs = g_biasP[j];
    float acc[8];
#pragma unroll
    for (int i = 0; i < 8; i++) acc[i] = g_TN[sni[rg * 8 + i] * G4 + j] + bs;
    for (int kc = 0; kc < ET; kc += 64) {
        __syncthreads();
        for (int f = t; f < 512; f += 256) {
            int rr = f >> 4, ks = f & 15;
            const float4 v = *(const float4*)&embT[(size_t)sti[rr] * ET + kc + ks * 4];
            sx[ks * 4 + 0][rr] = v.x; sx[ks * 4 + 1][rr] = v.y;
            sx[ks * 4 + 2][rr] = v.z; sx[ks * 4 + 3][rr] = v.w;
        }
        __syncthreads();
#pragma unroll 8
        for (int kk = 0; kk < 64; kk++) {
            float w = g_wihP[(EN + kc + kk) * G4 + j];
            float4 xa = *(float4*)&sx[kk][rg * 8];
            float4 xb = *(float4*)&sx[kk][rg * 8 + 4];
            acc[0] += xa.x * w; acc[1] += xa.y * w;
            acc[2] += xa.z * w; acc[3] += xa.w * w;
            acc[4] += xb.x * w; acc[5] += xb.y * w;
            acc[6] += xb.z * w; acc[7] += xb.w * w;
        }
    }
#pragma unroll
    for (int i = 0; i < 8; i++)
        g_GX[(size_t)(it * B + rg * 8 + i) * G4 + j] = acc[i];
}

// ------------- init h0/c0 -------------
__global__ void kInit() {
    int i = blockIdx.x * blockDim.x + threadIdx.x;
    if (i < B * H) { g_h[0][i] = 0.f; g_c[0][i] = 0.f; }
}

// ------------- S1 body: recurrent gates + cell update (128 threads) -------
__device__ __forceinline__ void s1_body(int it, int ublk, int t) {
    int p = it & 1, cur = p ^ 1;
    __shared__ float sh[64][33];   // scalar access only — pad 33 OK here
    int jj = t & 3, bb = t >> 2;
    int u = ublk * 4 + jj;
    float4 acc = make_float4(0.f, 0.f, 0.f, 0.f);
    for (int kc = 0; kc < H; kc += 64) {
        __syncthreads();
        for (int f = t; f < 512; f += 128) {
            int rr = f >> 4, ks = f & 15;
            const float4 v = *(const float4*)&g_h[p][rr * H + kc + ks * 4];
            sh[ks * 4 + 0][rr] = v.x; sh[ks * 4 + 1][rr] = v.y;
            sh[ks * 4 + 2][rr] = v.z; sh[ks * 4 + 3][rr] = v.w;
        }
        __syncthreads();
#pragma unroll 8
        for (int kk = 0; kk < 64; kk++) {
            const float4 w = *(const float4*)&g_whhP[(kc + kk) * G4 + u * 4];
            float x = sh[kk][bb];
            acc.x += w.x * x; acc.y += w.y * x;
            acc.z += w.z * x; acc.w += w.w * x;
        }
    }
    const float4 gx = *(const float4*)&g_GX[(size_t)(it * B + bb) * G4 + u * 4];
    float ig = acc.x + gx.x, fg = acc.y + gx.y;
    float gg = acc.z + gx.z, og = acc.w + gx.w;
    float cp = g_c[p][bb * H + u];
    float si = 1.f / (1.f + expf(-ig));
    float sf = 1.f / (1.f + expf(-fg));
    float so = 1.f / (1.f + expf(-og));
    float cn = sf * cp + si * tanhf(gg);
    float hn = so * tanhf(cn);
    g_c[cur][bb * H + u] = cn;
    g_h[cur][bb * H + u] = hn;
    g_hs[(size_t)(bb * L + it) * H + u] = hn;
}

// ------------- S4 body: s_t, z reductions, tl + topi (128 threads) -------
__device__ __forceinline__ void s4_body(int it, int b, int t, const int* __restrict__ tT,
                                        const float* __restrict__ Ws_w,
                                        const float* __restrict__ Ws_b,
                                        float* __restrict__ out, int out_size) {
    int cur = (it & 1) ^ 1;
    __shared__ float rf[128];
    __shared__ int ri[128];
    __shared__ float sS, sMx, sSz;
    __shared__ int sMi;

    // s_t = sigmoid([h,c] . Ws_w + Ws_b)
    float sp = 0.f;
    for (int k = t; k < 2 * H; k += 128)
        sp += ((k < H) ? g_h[cur][b * H + k] : g_c[cur][b * H + k - H]) * Ws_w[k];
    rf[t] = sp; __syncthreads();
    for (int s = 64; s; s >>= 1) { if (t < s) rf[t] += rf[t + s]; __syncthreads(); }
    if (t == 0) sS = 1.f / (1.f + expf(-(rf[0] + Ws_b[0])));
    __syncthreads();

    const float* zr0 = &g_z0[b * LDZ];
    const float* zr1 = &g_z1[b * LDZ];
    // pass 1: sum, max, argmax over z = z0 + z1
    float mx = -3.4e38f; int mi = 0; float sz = 0.f;
    for (int jx = t; jx < VO; jx += 128) {
        float v = zr0[jx] + zr1[jx];
        sz += v;
        if (v > mx) { mx = v; mi = jx; }
    }
    rf[t] = sz; __syncthreads();
    for (int s = 64; s; s >>= 1) { if (t < s) rf[t] += rf[t + s]; __syncthreads(); }
    if (t == 0) sSz = rf[0];
    __syncthreads();
    rf[t] = mx; ri[t] = mi; __syncthreads();
    for (int s = 64; s; s >>= 1) {
        if (t < s) {
            float v2 = rf[t + s]; int i2 = ri[t + s];
            if (v2 > rf[t] || (v2 == rf[t] && i2 < ri[t])) { rf[t] = v2; ri[t] = i2; }
        }
        __syncthreads();
    }
    if (t == 0) { sMx = rf[0]; sMi = ri[0]; }
    __syncthreads();
    // pass 2: sum exp(z - max)
    float mxv = sMx;
    float se = 0.f;
    for (int jx = t; jx < VO; jx += 128) se += expf(zr0[jx] + zr1[jx] - mxv);
    rf[t] = se; __syncthreads();
    for (int s = 64; s; s >>= 1) { if (t < s) rf[t] += rf[t + s]; __syncthreads(); }
    if (t == 0) {
        float lse = mxv + logf(rf[0]);
        float s = sS;
        int tc = tT[b * L + it];
        float tl;
        if (tc == EOFT) tl = 0.f;
        else {
            float ztc  = zr0[tc]   + zr1[tc];
            float zeof = zr0[EOFT] + zr1[EOFT];
            float out_tc  = s * (ztc  - lse);
            float out_eof = s * (zeof - lse);
            float Ssum    = s * (sSz - (float)VO * lse);
            const float smv = 0.1f / (float)(VO - 2);
            tl = 0.1f * logf(smv) + 0.9f * logf(0.9f)
               - smv * (Ssum - out_eof - out_tc) - 0.9f * out_tc;
        }
        g_tl[it * B + b] = tl;
        int oi = 1 + b * L + it;
        if (oi < out_size) out[oi] = (float)sMi;
    }
}

// ------------- fused per-step kernel: S1(it) || S4(it-1) -------------
__global__ void __launch_bounds__(128) kFuse(int it, const int* __restrict__ tT,
                                             const float* __restrict__ Ws_w,
                                             const float* __restrict__ Ws_b,
                                             float* __restrict__ out, int out_size) {
    if (blockIdx.x < 128) {
        s1_body(it, blockIdx.x, threadIdx.x);
    } else if (it > 0) {
        s4_body(it - 1, blockIdx.x - 128, threadIdx.x, tT, Ws_w, Ws_b, out, out_size);
    }
}

// ------------- standalone S4 for the last step -------------
__global__ void __launch_bounds__(128) kS4Last(int it, const int* __restrict__ tT,
                                               const float* __restrict__ Ws_w,
                                               const float* __restrict__ Ws_b,
                                               float* __restrict__ out, int out_size) {
    s4_body(it, blockIdx.x, threadIdx.x, tT, Ws_w, Ws_b, out, out_size);
}

// ------------- per-step S3: z = [h,c,h_parent] @ Wg^T + b, K-split x2 ------
// grid = 666 blocks (333 j-blocks x 2 k-halves), 128 threads.
// Warp lanes <-> 32 consecutive j (coalesced LDG.32 of Wg^T row);
// warp index <-> batch octet (acc[8] per thread).
__global__ void __launch_bounds__(128) kS3(int it, const int* __restrict__ pT,
                                           const float* __restrict__ Wg_b) {
    int cur = (it & 1) ^ 1;
    __shared__ float sx[64][PADW];   // PADW=36: 144B rows keep float4 reads 16B-aligned
    __shared__ int spar[32];
    int bx = blockIdx.x;
    int kh = (bx >= JB) ? 1 : 0;
    int jblk = bx - kh * JB;
    int khbase = kh * (KG / 2);             // 0 or 768
    int t = threadIdx.x;
    int lane = t & 31, wp = t >> 5;          // wp = batch octet 0..3
    int j = jblk * 32 + lane;
    if (t < 32) {
        int par = (it == 0) ? 0 : pT[t * L + it - 1];
        spar[t] = (it > 0 && par < it) ? par : -1;
    }
    float acc[8];
#pragma unroll
    for (int i = 0; i < 8; i++) acc[i] = 0.f;

    for (int kc = 0; kc < KG / 2; kc += 64) {
        __syncthreads();
        // fill sx[64][32] for k in [khbase+kc, khbase+kc+64)
        for (int f = t; f < 512; f += 128) {
            int rr = f >> 4, ks = f & 15;
            int k = khbase + kc + ks * 4;
            float4 v;
            if (k < H) v = *(const float4*)&g_h[cur][rr * H + k];
            else if (k < 2 * H) v = *(const float4*)&g_c[cur][rr * H + k - H];
            else {
                int par = spar[rr];
                v = (par >= 0) ? *(const float4*)&g_hs[(size_t)(rr * L + par) * H + k - 2 * H]
                               : make_float4(0.f, 0.f, 0.f, 0.f);
            }
            sx[ks * 4 + 0][rr] = v.x; sx[ks * 4 + 1][rr] = v.y;
            sx[ks * 4 + 2][rr] = v.z; sx[ks * 4 + 3][rr] = v.w;
        }
        __syncthreads();
        const float* wrow = &g_wgT[(size_t)(khbase + kc) * LDZ2 + j];
#pragma unroll 8
        for (int kk = 0; kk < 64; kk++) {
            float w = __ldg(wrow);
            wrow += LDZ2;
            float4 xa = *(float4*)&sx[kk][wp * 8];        // warp-broadcast, aligned
            float4 xb = *(float4*)&sx[kk][wp * 8 + 4];
            acc[0] += xa.x * w; acc[1] += xa.y * w;
            acc[2] += xa.z * w; acc[3] += xa.w * w;
            acc[4] += xb.x * w; acc[5] += xb.y * w;
            acc[6] += xb.z * w; acc[7] += xb.w * w;
        }
    }
    if (j < VO) {
        float* zp = kh ? g_z1 : g_z0;
        float bb = kh ? 0.f : Wg_b[j];
#pragma unroll
        for (int i = 0; i < 8; i++)
            zp[(wp * 8 + i) * LDZ + j] = acc[i] + bb;
    }
}

// ------------- final: sum tl, zero any tail -------------
__global__ void kFinal(float* __restrict__ out, int out_size) {
    __shared__ float rf[256];
    int t = threadIdx.x;
    float s = 0.f;
    for (int i = t; i < B * L; i += 256) s += g_tl[i];
    rf[t] = s; __syncthreads();
    for (int k = 128; k; k >>= 1) { if (t < k) rf[t] += rf[t + k]; __syncthreads(); }
    if (t == 0 && out_size > 0) out[0] = rf[0];
    for (int i = 1 + B * L + t; i < out_size; i += 256) out[i] = 0.f;
}

extern "C" void kernel_launch(void* const* d_in, const int* in_sizes, int n_in,
                              void* d_out, int out_size) {
    const int*   nT   = (const int*)d_in[0];
    const int*   tT   = (const int*)d_in[1];
    const int*   pT   = (const int*)d_in[2];
    const float* embN = (const float*)d_in[3];
    const float* embT = (const float*)d_in[4];
    const float* w_ih = (const float*)d_in[5];
    const float* w_hh = (const float*)d_in[6];
    const float* b_ih = (const float*)d_in[7];
    const float* b_hh = (const float*)d_in[8];
    // d_in[9..12] (Wh_w, Wh_b, v_w, v_b) are dead code — attention branch never wins.
    const float* Wg_w = (const float*)d_in[13];
    const float* Wg_b = (const float*)d_in[14];
    const float* Ws_w = (const float*)d_in[15];
    const float* Ws_b = (const float*)d_in[16];
    float* out = (float*)d_out;

    kPrep<<<1024, 256>>>(w_ih, w_hh, b_ih, b_hh);
    kPrepWg<<<dim3(LDZ2 / 32, KG / 32), dim3(32, 8)>>>(Wg_w);
    kTN<<<dim3(G4 / 256, (VN + 7) / 8), 256>>>(embN);
    kGX<<<dim3(G4 / 64, L), 256>>>(embT, nT, tT);
    kInit<<<(B * H + 255) / 256, 256>>>();

    for (int it = 0; it < L; ++it) {
        kFuse<<<160, 128>>>(it, tT, Ws_w, Ws_b, out, out_size);
        kS3<<<2 * JB, 128>>>(it, pT, Wg_b);
    }
    kS4Last<<<B, 128>>>(127, tT, Ws_w, Ws_b, out, out_size);
    kFinal<<<1, 256>>>(out, out_size);
}

// round 16
// speedup vs baseline: 2.5456x; 1.6049x over previous
#include <cuda_runtime.h>
#include <math.h>

#define B  32
#define L  128
#define H  512
#define EN 256
#define ET 512
#define VN 300
#define VO 10053
#define EOFT 9999
#define G4 2048
#define KG 1536
#define LDZ 10080        // z row stride (multiple of 32)
#define LDZ2 10656       // padded Wg^T columns = 333*32
#define JB 333           // j-blocks of 32 cols
#define PADW 36          // smem row pad: 36 floats = 144B, 16B-aligned rows

typedef unsigned long long u64;

// ---- packed f32x2 helpers (sm_103a FFMA2) — IEEE-identical per lane ----
__device__ __forceinline__ u64 pk2(float a, float b) {
    u64 r; asm("mov.b64 %0, {%1, %2};" : "=l"(r) : "f"(a), "f"(b)); return r;
}
__device__ __forceinline__ void upk2(u64 v, float& a, float& b) {
    asm("mov.b64 {%0, %1}, %2;" : "=f"(a), "=f"(b) : "l"(v));
}
__device__ __forceinline__ u64 fma2(u64 a, u64 b, u64 c) {
    u64 d; asm("fma.rn.f32x2 %0, %1, %2, %3;" : "=l"(d) : "l"(a), "l"(b), "l"(c));
    return d;
}

// ------------- static device scratch (no allocations) -------------
__device__ float g_wihP[(EN + ET) * G4];      // [k][u*4+g]
__device__ float g_whhP[H * G4];              // [k][u*4+g]
__device__ float g_biasP[G4];                 // permuted b_ih+b_hh
__device__ float g_wgT[(size_t)KG * LDZ2];    // [k][j], j >= VO zeroed
__device__ float g_TN[VN * G4];               // embN @ w_ihN^T (permuted cols)
__device__ float g_GX[B * L * G4];            // hoisted input-side gates
__device__ float g_h[3][B * H];               // triple-buffered: h(it) at it%3
__device__ float g_c[3][B * H];
__device__ float g_hs[B * L * H];
__device__ float g_z0[2][B * LDZ];            // K-split low half, double-buffered (it&1)
__device__ float g_z1[2][B * LDZ];            // K-split high half
__device__ float g_tl[B * L];

// ------------- prep: permute w_ih / w_hh / bias -------------
__global__ void kPrep(const float* __restrict__ w_ih, const float* __restrict__ w_hh,
                      const float* __restrict__ b_ih, const float* __restrict__ b_hh) {
    const int n1 = G4 * (EN + ET), n2 = G4 * H;
    for (int i = blockIdx.x * blockDim.x + threadIdx.x; i < n1 + n2 + G4;
         i += gridDim.x * blockDim.x) {
        if (i < n1) {
            int j = i / (EN + ET), k = i % (EN + ET);
            g_wihP[k * G4 + (j & 511) * 4 + (j >> 9)] = w_ih[i];
        } else if (i < n1 + n2) {
            int e = i - n1;
            int j = e / H, k = e % H;
            g_whhP[k * G4 + (j & 511) * 4 + (j >> 9)] = w_hh[e];
        } else {
            int j = i - n1 - n2;
            g_biasP[(j & 511) * 4 + (j >> 9)] = b_ih[j] + b_hh[j];
        }
    }
}

// ------------- prep: transpose Wg_w [VO][KG] -> g_wgT[k][LDZ2] -------------
__global__ void kPrepWg(const float* __restrict__ Wg_w) {
    __shared__ float tile[32][33];
    int j0 = blockIdx.x * 32, k0 = blockIdx.y * 32;
    int tx = threadIdx.x, ty = threadIdx.y;  // 32 x 8
#pragma unroll
    for (int i = 0; i < 32; i += 8) {
        int j = j0 + ty + i, k = k0 + tx;
        tile[ty + i][tx] = (j < VO) ? Wg_w[(size_t)j * KG + k] : 0.f;
    }
    __syncthreads();
#pragma unroll
    for (int i = 0; i < 32; i += 8) {
        int k = k0 + ty + i, j = j0 + tx;
        g_wgT[(size_t)k * LDZ2 + j] = tile[tx][ty + i];
    }
}

// ------------- prep: TN[v][j'] = embN[v] . w_ihN[j'] -------------
__global__ void __launch_bounds__(256) kTN(const float* __restrict__ embN) {
    __shared__ float se[8][EN];
    int t = threadIdx.x;
    int j = blockIdx.x * 256 + t;
    int v0 = blockIdx.y * 8;
    for (int f = t; f < 8 * EN; f += 256) {
        int vv = f >> 8, k = f & 255;
        int v = v0 + vv;
        se[vv][k] = (v < VN) ? embN[v * EN + k] : 0.f;
    }
    __syncthreads();
    float acc[8];
#pragma unroll
    for (int i = 0; i < 8; i++) acc[i] = 0.f;
    for (int k = 0; k < EN; k++) {
        float w = g_wihP[k * G4 + j];
#pragma unroll
        for (int vv = 0; vv < 8; vv++) acc[vv] += se[vv][k] * w;
    }
#pragma unroll
    for (int vv = 0; vv < 8; vv++) {
        int v = v0 + vv;
        if (v < VN) g_TN[v * G4 + j] = acc[vv];
    }
}

// ------------- prep: GX[(it*B+b)][j'] = TN[n] + embT[t].w_ihT + bias ------
__global__ void __launch_bounds__(256) kGX(const float* __restrict__ embT,
                                           const int* __restrict__ nT,
                                           const int* __restrict__ tT) {
    __shared__ float sx[64][PADW];
    __shared__ int sti[32], sni[32];
    int t = threadIdx.x;
    int jj = t & 63, rg = t >> 6;
    int it = blockIdx.y;
    int j = blockIdx.x * 64 + jj;
    if (t < 32) {
        sti[t] = (it == 0) ? 0 : tT[t * L + it - 1];
        sni[t] = (it == 0) ? 0 : nT[t * L + it - 1];
    }
    __syncthreads();
    float bs = g_biasP[j];
    u64 acc2[4];
#pragma unroll
    for (int i = 0; i < 4; i++) {
        float a0 = g_TN[sni[rg * 8 + 2 * i] * G4 + j] + bs;
        float a1 = g_TN[sni[rg * 8 + 2 * i + 1] * G4 + j] + bs;
        acc2[i] = pk2(a0, a1);
    }
    for (int kc = 0; kc < ET; kc += 64) {
        __syncthreads();
        for (int f = t; f < 512; f += 256) {
            int rr = f >> 4, ks = f & 15;
            const float4 v = *(const float4*)&embT[(size_t)sti[rr] * ET + kc + ks * 4];
            sx[ks * 4 + 0][rr] = v.x; sx[ks * 4 + 1][rr] = v.y;
            sx[ks * 4 + 2][rr] = v.z; sx[ks * 4 + 3][rr] = v.w;
        }
        __syncthreads();
#pragma unroll 8
        for (int kk = 0; kk < 64; kk++) {
            float w = g_wihP[(EN + kc + kk) * G4 + j];
            u64 w2 = pk2(w, w);
            ulonglong2 va = *(const ulonglong2*)&sx[kk][rg * 8];
            ulonglong2 vb = *(const ulonglong2*)&sx[kk][rg * 8 + 4];
            acc2[0] = fma2(va.x, w2, acc2[0]);
            acc2[1] = fma2(va.y, w2, acc2[1]);
            acc2[2] = fma2(vb.x, w2, acc2[2]);
            acc2[3] = fma2(vb.y, w2, acc2[3]);
        }
    }
#pragma unroll
    for (int i = 0; i < 4; i++) {
        float a0, a1; upk2(acc2[i], a0, a1);
        g_GX[(size_t)(it * B + rg * 8 + 2 * i) * G4 + j]     = a0;
        g_GX[(size_t)(it * B + rg * 8 + 2 * i + 1) * G4 + j] = a1;
    }
}

// ------------- init: zero the h(-1)/c(-1) buffer (index 2) -------------
__global__ void kInit() {
    int i = blockIdx.x * blockDim.x + threadIdx.x;
    if (i < B * H) { g_h[2][i] = 0.f; g_c[2][i] = 0.f; }
}

// ------------- S1 body: recurrent gates + cell update (128 threads) -------
// h(it) stored at buffer it%3; reads buffer (it+2)%3.
__device__ __forceinline__ void s1_body(int it, int ublk, int t) {
    int p = (it + 2) % 3, cur = it % 3;
    __shared__ float sh[64][33];   // scalar access only
    int jj = t & 3, bb = t >> 2;
    int u = ublk * 4 + jj;
    u64 accA = 0ULL, accB = 0ULL;  // (i,f) and (g,o) gate pairs
    for (int kc = 0; kc < H; kc += 64) {
        __syncthreads();
        for (int f = t; f < 512; f += 128) {
            int rr = f >> 4, ks = f & 15;
            const float4 v = *(const float4*)&g_h[p][rr * H + kc + ks * 4];
            sh[ks * 4 + 0][rr] = v.x; sh[ks * 4 + 1][rr] = v.y;
            sh[ks * 4 + 2][rr] = v.z; sh[ks * 4 + 3][rr] = v.w;
        }
        __syncthreads();
#pragma unroll 8
        for (int kk = 0; kk < 64; kk++) {
            const ulonglong2 w = *(const ulonglong2*)&g_whhP[(kc + kk) * G4 + u * 4];
            float x = sh[kk][bb];
            u64 xx = pk2(x, x);
            accA = fma2(w.x, xx, accA);
            accB = fma2(w.y, xx, accB);
        }
    }
    float ai, af, ag, ao;
    upk2(accA, ai, af); upk2(accB, ag, ao);
    const float4 gx = *(const float4*)&g_GX[(size_t)(it * B + bb) * G4 + u * 4];
    float ig = ai + gx.x, fg = af + gx.y;
    float gg = ag + gx.z, og = ao + gx.w;
    float cp = g_c[p][bb * H + u];
    float si = 1.f / (1.f + expf(-ig));
    float sf = 1.f / (1.f + expf(-fg));
    float so = 1.f / (1.f + expf(-og));
    float cn = sf * cp + si * tanhf(gg);
    float hn = so * tanhf(cn);
    g_c[cur][bb * H + u] = cn;
    g_h[cur][bb * H + u] = hn;
    g_hs[(size_t)(bb * L + it) * H + u] = hn;
}

// ------------- S3 body: z[it&1] = [h,c,h_parent] @ Wg^T + b, K-split x2 ----
__device__ __forceinline__ void s3_body(int it, int bx, int t,
                                        const int* __restrict__ pT,
                                        const float* __restrict__ Wg_b) {
    int cur = it % 3;
    __shared__ float sx[64][PADW];   // 144B rows keep 16B alignment
    __shared__ int spar[32];
    int kh = (bx >= JB) ? 1 : 0;
    int jblk = bx - kh * JB;
    int khbase = kh * (KG / 2);             // 0 or 768
    int lane = t & 31, wp = t >> 5;          // wp = batch octet 0..3
    int j = jblk * 32 + lane;
    if (t < 32) {
        int par = (it == 0) ? 0 : pT[t * L + it - 1];
        spar[t] = (it > 0 && par < it) ? par : -1;
    }
    u64 acc2[4];
#pragma unroll
    for (int i = 0; i < 4; i++) acc2[i] = 0ULL;

    for (int kc = 0; kc < KG / 2; kc += 64) {
        __syncthreads();
        for (int f = t; f < 512; f += 128) {
            int rr = f >> 4, ks = f & 15;
            int k = khbase + kc + ks * 4;
            float4 v;
            if (k < H) v = *(const float4*)&g_h[cur][rr * H + k];
            else if (k < 2 * H) v = *(const float4*)&g_c[cur][rr * H + k - H];
            else {
                int par = spar[rr];
                v = (par >= 0) ? *(const float4*)&g_hs[(size_t)(rr * L + par) * H + k - 2 * H]
                               : make_float4(0.f, 0.f, 0.f, 0.f);
            }
            sx[ks * 4 + 0][rr] = v.x; sx[ks * 4 + 1][rr] = v.y;
            sx[ks * 4 + 2][rr] = v.z; sx[ks * 4 + 3][rr] = v.w;
        }
        __syncthreads();
        const float* wrow = &g_wgT[(size_t)(khbase + kc) * LDZ2 + j];
#pragma unroll 8
        for (int kk = 0; kk < 64; kk++) {
            float w = __ldg(wrow);
            wrow += LDZ2;
            u64 w2 = pk2(w, w);
            ulonglong2 va = *(const ulonglong2*)&sx[kk][wp * 8];     // aligned
            ulonglong2 vb = *(const ulonglong2*)&sx[kk][wp * 8 + 4];
            acc2[0] = fma2(va.x, w2, acc2[0]);
            acc2[1] = fma2(va.y, w2, acc2[1]);
            acc2[2] = fma2(vb.x, w2, acc2[2]);
            acc2[3] = fma2(vb.y, w2, acc2[3]);
        }
    }
    if (j < VO) {
        float* zp = kh ? g_z1[it & 1] : g_z0[it & 1];
        float bb = kh ? 0.f : Wg_b[j];
#pragma unroll
        for (int i = 0; i < 4; i++) {
            float a0, a1; upk2(acc2[i], a0, a1);
            zp[(wp * 8 + 2 * i) * LDZ + j]     = a0 + bb;
            zp[(wp * 8 + 2 * i + 1) * LDZ + j] = a1 + bb;
        }
    }
}

// ------------- S4 body: s_t, z reductions, tl + topi (128 threads) -------
__device__ __forceinline__ void s4_body(int it, int b, int t, const int* __restrict__ tT,
                                        const float* __restrict__ Ws_w,
                                        const float* __restrict__ Ws_b,
                                        float* __restrict__ out, int out_size) {
    int cur = it % 3;
    __shared__ float rf[128];
    __shared__ int ri[128];
    __shared__ float sS, sMx, sSz;
    __shared__ int sMi;

    // s_t = sigmoid([h,c] . Ws_w + Ws_b)
    float sp = 0.f;
    for (int k = t; k < 2 * H; k += 128)
        sp += ((k < H) ? g_h[cur][b * H + k] : g_c[cur][b * H + k - H]) * Ws_w[k];
    rf[t] = sp; __syncthreads();
    for (int s = 64; s; s >>= 1) { if (t < s) rf[t] += rf[t + s]; __syncthreads(); }
    if (t == 0) sS = 1.f / (1.f + expf(-(rf[0] + Ws_b[0])));
    __syncthreads();

    const float* zr0 = &g_z0[it & 1][b * LDZ];
    const float* zr1 = &g_z1[it & 1][b * LDZ];
    // pass 1: sum, max, argmax over z = z0 + z1
    float mx = -3.4e38f; int mi = 0; float sz = 0.f;
    for (int jx = t; jx < VO; jx += 128) {
        float v = zr0[jx] + zr1[jx];
        sz += v;
        if (v > mx) { mx = v; mi = jx; }
    }
    rf[t] = sz; __syncthreads();
    for (int s = 64; s; s >>= 1) { if (t < s) rf[t] += rf[t + s]; __syncthreads(); }
    if (t == 0) sSz = rf[0];
    __syncthreads();
    rf[t] = mx; ri[t] = mi; __syncthreads();
    for (int s = 64; s; s >>= 1) {
        if (t < s) {
            float v2 = rf[t + s]; int i2 = ri[t + s];
            if (v2 > rf[t] || (v2 == rf[t] && i2 < ri[t])) { rf[t] = v2; ri[t] = i2; }
        }
        __syncthreads();
    }
    if (t == 0) { sMx = rf[0]; sMi = ri[0]; }
    __syncthreads();
    // pass 2: sum exp(z - max)
    float mxv = sMx;
    float se = 0.f;
    for (int jx = t; jx < VO; jx += 128) se += expf(zr0[jx] + zr1[jx] - mxv);
    rf[t] = se; __syncthreads();
    for (int s = 64; s; s >>= 1) { if (t < s) rf[t] += rf[t + s]; __syncthreads(); }
    if (t == 0) {
        float lse = mxv + logf(rf[0]);
        float s = sS;
        int tc = tT[b * L + it];
        float tl;
        if (tc == EOFT) tl = 0.f;
        else {
            float ztc  = zr0[tc]   + zr1[tc];
            float zeof = zr0[EOFT] + zr1[EOFT];
            float out_tc  = s * (ztc  - lse);
            float out_eof = s * (zeof - lse);
            float Ssum    = s * (sSz - (float)VO * lse);
            const float smv = 0.1f / (float)(VO - 2);
            tl = 0.1f * logf(smv) + 0.9f * logf(0.9f)
               - smv * (Ssum - out_eof - out_tc) - 0.9f * out_tc;
        }
        g_tl[it * B + b] = tl;
        int oi = 1 + b * L + it;
        if (oi < out_size) out[oi] = (float)sMi;
    }
}

// ------------- prologue: S1(0) -------------
__global__ void __launch_bounds__(128) kS1First() {
    s1_body(0, blockIdx.x, threadIdx.x);
}

// ------------- per-step merged kernel: S3(s) || S1(s+1) || S4(s-1) --------
// Hazard-free: h/c triple-buffered (s-1, s, s+1 distinct mod 3),
// z double-buffered (S3 writes s&1, S4 reads (s-1)&1), g_hs rows disjoint.
__global__ void __launch_bounds__(128) kStep(int s, const int* __restrict__ pT,
                                             const float* __restrict__ Wg_b,
                                             const int* __restrict__ tT,
                                             const float* __restrict__ Ws_w,
                                             const float* __restrict__ Ws_b,
                                             float* __restrict__ out, int out_size) {
    int bx = blockIdx.x;
    if (bx < 2 * JB) {
        s3_body(s, bx, threadIdx.x, pT, Wg_b);
    } else if (bx < 2 * JB + 128) {
        if (s < L - 1) s1_body(s + 1, bx - 2 * JB, threadIdx.x);
    } else {
        if (s > 0) s4_body(s - 1, bx - 2 * JB - 128, threadIdx.x, tT, Ws_w, Ws_b, out, out_size);
    }
}

// ------------- epilogue: S4(127) -------------
__global__ void __launch_bounds__(128) kS4Last(const int* __restrict__ tT,
                                               const float* __restrict__ Ws_w,
                                               const float* __restrict__ Ws_b,
                                               float* __restrict__ out, int out_size) {
    s4_body(L - 1, blockIdx.x, threadIdx.x, tT, Ws_w, Ws_b, out, out_size);
}

// ------------- final: sum tl, zero any tail -------------
__global__ void kFinal(float* __restrict__ out, int out_size) {
    __shared__ float rf[256];
    int t = threadIdx.x;
    float s = 0.f;
    for (int i = t; i < B * L; i += 256) s += g_tl[i];
    rf[t] = s; __syncthreads();
    for (int k = 128; k; k >>= 1) { if (t < k) rf[t] += rf[t + k]; __syncthreads(); }
    if (t == 0 && out_size > 0) out[0] = rf[0];
    for (int i = 1 + B * L + t; i < out_size; i += 256) out[i] = 0.f;
}

extern "C" void kernel_launch(void* const* d_in, const int* in_sizes, int n_in,
                              void* d_out, int out_size) {
    const int*   nT   = (const int*)d_in[0];
    const int*   tT   = (const int*)d_in[1];
    const int*   pT   = (const int*)d_in[2];
    const float* embN = (const float*)d_in[3];
    const float* embT = (const float*)d_in[4];
    const float* w_ih = (const float*)d_in[5];
    const float* w_hh = (const float*)d_in[6];
    const float* b_ih = (const float*)d_in[7];
    const float* b_hh = (const float*)d_in[8];
    // d_in[9..12] (Wh_w, Wh_b, v_w, v_b) are dead code — attention branch never wins.
    const float* Wg_w = (const float*)d_in[13];
    const float* Wg_b = (const float*)d_in[14];
    const float* Ws_w = (const float*)d_in[15];
    const float* Ws_b = (const float*)d_in[16];
    float* out = (float*)d_out;

    kPrep<<<1024, 256>>>(w_ih, w_hh, b_ih, b_hh);
    kPrepWg<<<dim3(LDZ2 / 32, KG / 32), dim3(32, 8)>>>(Wg_w);
    kTN<<<dim3(G4 / 256, (VN + 7) / 8), 256>>>(embN);
    kGX<<<dim3(G4 / 64, L), 256>>>(embT, nT, tT);
    kInit<<<(B * H + 255) / 256, 256>>>();
    kS1First<<<128, 128>>>();

    for (int s = 0; s < L; ++s)
        kStep<<<2 * JB + 160, 128>>>(s, pT, Wg_b, tT, Ws_w, Ws_b, out, out_size);

    kS4Last<<<B, 128>>>(tT, Ws_w, Ws_b, out, out_size);
    kFinal<<<1, 256>>>(out, out_size);
}